// round 1
// baseline (speedup 1.0000x reference)
#include <cuda_runtime.h>
#include <cstddef>

#define NN 50000
#define NE 400000
#define DD 128

// Scratch (device globals: allocation-free rule)
__device__ float g_K[NN * DD];
__device__ float g_Q[NN * DD];
__device__ float g_V[NN * DD];
__device__ float g_H[NN * DD];   // layer-1 accumulator, then relu'd input to layer 2
__device__ int   g_is32;

struct GemmArgs {
    const float* W[4];
    float*       dst[4];   // dst[0..2] = K,Q,V ; dst[3] = skip accumulator
    const float* bias;     // added to dst[3]
};

// ---------------------------------------------------------------------------
// int32-vs-int64 edge_index detection.
// int64 layout: odd 32-bit words are high words of values in [0, 50000) -> 0.
// int32 layout: odd words are real indices, statistically nonzero somewhere.
// ---------------------------------------------------------------------------
__global__ void detect_init_kernel() { g_is32 = 0; }

__global__ void detect_kernel(const unsigned int* __restrict__ w) {
    int i = blockIdx.x * blockDim.x + threadIdx.x;
    if (i >= NE) return;                 // safe: reads words [1, 2*NE) < 800000
    if (w[2 * i + 1] != 0u) atomicOr(&g_is32, 1);
}

// ---------------------------------------------------------------------------
// Fused 4-way projection GEMM:  dst[w] = A @ W[w]   (w = 0..3)
// dst[3] gets + bias (skip path).  Optional ReLU applied to A at load
// (used for layer 2 so no separate elementwise pass is needed).
// Tile: BM=64, BN=64, BK=32; 256 threads; 4x4 micro-tile per thread.
// grid = (ceil(N/64), 2, 4)
// ---------------------------------------------------------------------------
__global__ void __launch_bounds__(256) gemm4_kernel(
    const float* __restrict__ A, GemmArgs ga, int apply_relu)
{
    __shared__ float As[64][33];   // [row-in-tile][k-in-chunk], padded
    __shared__ float Bs[32][64];   // [k-in-chunk][col-in-tile]

    const int w = blockIdx.z;
    const float* __restrict__ W = ga.W[w];
    float* __restrict__ dst = ga.dst[w];

    const int row0 = blockIdx.x * 64;
    const int col0 = blockIdx.y * 64;
    const int t  = threadIdx.x;
    const int tx = t & 15;
    const int ty = t >> 4;

    float acc[4][4] = {};

    for (int k0 = 0; k0 < DD; k0 += 32) {
        // Load A tile: 64x32, coalesced (32 consecutive k per row chunk)
        #pragma unroll
        for (int l = 0; l < 8; l++) {
            int idx = l * 256 + t;
            int r = idx >> 5, c = idx & 31;
            int grow = row0 + r;
            float v = (grow < NN) ? A[(size_t)grow * DD + k0 + c] : 0.f;
            if (apply_relu) v = fmaxf(v, 0.f);
            As[r][c] = v;
        }
        // Load B tile: 32x64, coalesced
        #pragma unroll
        for (int l = 0; l < 8; l++) {
            int idx = l * 256 + t;
            int r = idx >> 6, c = idx & 63;
            Bs[r][c] = W[(size_t)(k0 + r) * DD + col0 + c];
        }
        __syncthreads();

        #pragma unroll
        for (int kk = 0; kk < 32; kk++) {
            float a[4], b[4];
            #pragma unroll
            for (int i = 0; i < 4; i++) a[i] = As[ty * 4 + i][kk];
            #pragma unroll
            for (int j = 0; j < 4; j++) b[j] = Bs[kk][tx * 4 + j];
            #pragma unroll
            for (int i = 0; i < 4; i++)
                #pragma unroll
                for (int j = 0; j < 4; j++)
                    acc[i][j] = fmaf(a[i], b[j], acc[i][j]);
        }
        __syncthreads();
    }

    const bool add_bias = (w == 3);
    #pragma unroll
    for (int i = 0; i < 4; i++) {
        int grow = row0 + ty * 4 + i;
        if (grow >= NN) break;
        #pragma unroll
        for (int j = 0; j < 4; j++) {
            int gcol = col0 + tx * 4 + j;
            float v = acc[i][j];
            if (add_bias) v += ga.bias[gcol];
            dst[(size_t)grow * DD + gcol] = v;
        }
    }
}

// ---------------------------------------------------------------------------
// Edge kernel: one warp per edge. Each lane handles 4 consecutive features.
//   eta = sigmoid(K[tgt] + Q[src]);  msg = eta * V[src];  atomicAdd to out[tgt]
// ---------------------------------------------------------------------------
__global__ void __launch_bounds__(256) edge_kernel(
    const void* __restrict__ edge_index,
    const float* __restrict__ K, const float* __restrict__ Q,
    const float* __restrict__ V, float* __restrict__ out)
{
    int warp = (blockIdx.x * blockDim.x + threadIdx.x) >> 5;
    if (warp >= NE) return;
    int lane = threadIdx.x & 31;

    int src, tgt;
    if (g_is32) {
        const int* ei = (const int*)edge_index;
        src = ei[warp];
        tgt = ei[NE + warp];
    } else {
        const long long* ei = (const long long*)edge_index;
        src = (int)ei[warp];
        tgt = (int)ei[NE + warp];
    }

    int d0 = lane * 4;
    float4 kt = *(const float4*)&K[(size_t)tgt * DD + d0];
    float4 qs = *(const float4*)&Q[(size_t)src * DD + d0];
    float4 vs = *(const float4*)&V[(size_t)src * DD + d0];

    float4 m;
    m.x = vs.x / (1.f + __expf(-(kt.x + qs.x)));
    m.y = vs.y / (1.f + __expf(-(kt.y + qs.y)));
    m.z = vs.z / (1.f + __expf(-(kt.z + qs.z)));
    m.w = vs.w / (1.f + __expf(-(kt.w + qs.w)));

    float* o = &out[(size_t)tgt * DD + d0];
    atomicAdd(o + 0, m.x);
    atomicAdd(o + 1, m.y);
    atomicAdd(o + 2, m.z);
    atomicAdd(o + 3, m.w);
}

// ---------------------------------------------------------------------------
extern "C" void kernel_launch(void* const* d_in, const int* in_sizes, int n_in,
                              void* d_out, int out_size)
{
    const float* x   = (const float*)d_in[0];
    const void*  ei  = d_in[1];
    const float* Wk1 = (const float*)d_in[2];
    const float* Wq1 = (const float*)d_in[3];
    const float* Wv1 = (const float*)d_in[4];
    const float* Ws1 = (const float*)d_in[5];
    const float* b1  = (const float*)d_in[6];
    const float* Wk2 = (const float*)d_in[7];
    const float* Wq2 = (const float*)d_in[8];
    const float* Wv2 = (const float*)d_in[9];
    const float* Ws2 = (const float*)d_in[10];
    const float* b2  = (const float*)d_in[11];
    float* out = (float*)d_out;

    // Device-global scratch addresses (query only; no allocation)
    float *pK, *pQ, *pV, *pH;
    cudaGetSymbolAddress((void**)&pK, g_K);
    cudaGetSymbolAddress((void**)&pQ, g_Q);
    cudaGetSymbolAddress((void**)&pV, g_V);
    cudaGetSymbolAddress((void**)&pH, g_H);

    // dtype detection for edge_index
    detect_init_kernel<<<1, 1>>>();
    detect_kernel<<<(NE + 255) / 256, 256>>>((const unsigned int*)ei);

    dim3 ggrid((NN + 63) / 64, 2, 4);
    dim3 gblk(256);
    dim3 egrid((NE * 32 + 255) / 256);  // one warp per edge, 8 warps/block

    // ---- Layer 1 ----
    GemmArgs g1;
    g1.W[0] = Wk1; g1.W[1] = Wq1; g1.W[2] = Wv1; g1.W[3] = Ws1;
    g1.dst[0] = pK; g1.dst[1] = pQ; g1.dst[2] = pV; g1.dst[3] = pH;
    g1.bias = b1;
    gemm4_kernel<<<ggrid, gblk>>>(x, g1, /*relu=*/0);
    edge_kernel<<<egrid, 256>>>(ei, pK, pQ, pV, pH);

    // ---- Layer 2 (ReLU fused into A-load) ----
    GemmArgs g2;
    g2.W[0] = Wk2; g2.W[1] = Wq2; g2.W[2] = Wv2; g2.W[3] = Ws2;
    g2.dst[0] = pK; g2.dst[1] = pQ; g2.dst[2] = pV; g2.dst[3] = out;
    g2.bias = b2;
    gemm4_kernel<<<ggrid, gblk>>>(pH, g2, /*relu=*/1);
    edge_kernel<<<egrid, 256>>>(ei, pK, pQ, pV, out);
}

// round 2
// speedup vs baseline: 1.5992x; 1.5992x over previous
#include <cuda_runtime.h>
#include <cstddef>
#include <cstdint>

#define NN 50000
#define NE 400000
#define DD 128

// Scratch (device globals: allocation-free rule)
__device__ float g_K[NN * DD];
__device__ float g_Q[NN * DD];
__device__ float g_V[NN * DD];
__device__ float g_H[NN * DD];
__device__ int   g_is32;

struct GemmArgs {
    const float* W[4];
    float*       dst[4];   // dst[0..2] = K,Q,V ; dst[3] = skip accumulator
    const float* bias;     // added to dst[3]
};

// ---------------------------------------------------------------------------
// int32-vs-int64 edge_index detection (odd 32-bit words all zero => int64).
// ---------------------------------------------------------------------------
__global__ void detect_init_kernel() { g_is32 = 0; }

__global__ void detect_kernel(const unsigned int* __restrict__ w) {
    int i = blockIdx.x * blockDim.x + threadIdx.x;
    if (i >= NE) return;
    if (w[2 * i + 1] != 0u) atomicOr(&g_is32, 1);
}

// ---------------------------------------------------------------------------
// Fused 4-way projection GEMM using packed fma.rn.f32x2 (FFMA2).
//   dst[w] = act(A) @ W[w],  w = 0..3 ; dst[3] += bias (skip path)
// BM=128, BN=128(=D), BK=16. 256 threads, 8x8 micro-tile per thread.
// A stored in smem PRE-DUPLICATED as float2{a,a} so the FFMA2 broadcast
// operand needs no per-iteration packing. B read as natural f32x2 pairs.
// grid = (ceil(N/128), 4)
// ---------------------------------------------------------------------------
#define BM 128
#define BK 16

typedef unsigned long long u64;

__device__ __forceinline__ u64 ffma2(u64 a, u64 b, u64 c) {
    u64 d;
    asm("fma.rn.f32x2 %0, %1, %2, %3;" : "=l"(d) : "l"(a), "l"(b), "l"(c));
    return d;
}

__global__ void __launch_bounds__(256, 2) gemm4_kernel(
    const float* __restrict__ A, GemmArgs ga, int apply_relu)
{
    __shared__ float2 AsD[BM][BK + 1];   // [row][k], value duplicated {a,a}
    __shared__ float  Bs[BK][DD + 4];    // [k][col]

    const int w = blockIdx.y;
    const float* __restrict__ W = ga.W[w];
    float* __restrict__ dst = ga.dst[w];

    const int row0 = blockIdx.x * BM;
    const int t  = threadIdx.x;
    const int tx = t & 15;        // column group: cols tx*8 .. tx*8+7
    const int ty = t >> 4;        // row group:    rows ty*8 .. ty*8+7

    u64 acc[8][4];                // 8 rows x 4 f32x2 col-pairs
    #pragma unroll
    for (int i = 0; i < 8; i++)
        #pragma unroll
        for (int j = 0; j < 4; j++) acc[i][j] = 0ull;   // bitwise {0.f,0.f}

    for (int k0 = 0; k0 < DD; k0 += BK) {
        // ---- Load A tile (128 x 16): 512 float4, 2 per thread ----
        #pragma unroll
        for (int l = 0; l < 2; l++) {
            int idx = l * 256 + t;            // float4 index
            int r   = idx >> 2;               // row in tile (4 float4 per row)
            int c4  = (idx & 3) * 4;          // k offset
            int grow = row0 + r;
            float4 v = make_float4(0.f, 0.f, 0.f, 0.f);
            if (grow < NN) v = *(const float4*)&A[(size_t)grow * DD + k0 + c4];
            if (apply_relu) {
                v.x = fmaxf(v.x, 0.f); v.y = fmaxf(v.y, 0.f);
                v.z = fmaxf(v.z, 0.f); v.w = fmaxf(v.w, 0.f);
            }
            AsD[r][c4 + 0] = make_float2(v.x, v.x);
            AsD[r][c4 + 1] = make_float2(v.y, v.y);
            AsD[r][c4 + 2] = make_float2(v.z, v.z);
            AsD[r][c4 + 3] = make_float2(v.w, v.w);
        }
        // ---- Load B tile (16 x 128): 512 float4, 2 per thread ----
        #pragma unroll
        for (int l = 0; l < 2; l++) {
            int idx = l * 256 + t;
            int r   = idx >> 5;               // k row (32 float4 per row)
            int c4  = (idx & 31) * 4;
            float4 v = *(const float4*)&W[(size_t)(k0 + r) * DD + c4];
            *(float4*)&Bs[r][c4] = v;
        }
        __syncthreads();

        #pragma unroll
        for (int kk = 0; kk < BK; kk++) {
            u64 a[8], b[4];
            #pragma unroll
            for (int i = 0; i < 8; i++)
                a[i] = *(const u64*)&AsD[ty * 8 + i][kk];
            const float* brow = &Bs[kk][tx * 8];
            #pragma unroll
            for (int j = 0; j < 4; j++)
                b[j] = *(const u64*)&brow[2 * j];
            #pragma unroll
            for (int i = 0; i < 8; i++)
                #pragma unroll
                for (int j = 0; j < 4; j++)
                    acc[i][j] = ffma2(a[i], b[j], acc[i][j]);
        }
        __syncthreads();
    }

    // ---- Epilogue ----
    const bool add_bias = (w == 3);
    float bias8[8];
    if (add_bias) {
        #pragma unroll
        for (int j = 0; j < 8; j++) bias8[j] = ga.bias[tx * 8 + j];
    }

    union { u64 u; float2 f; } cv;
    #pragma unroll
    for (int i = 0; i < 8; i++) {
        int grow = row0 + ty * 8 + i;
        if (grow >= NN) break;
        float o[8];
        #pragma unroll
        for (int j = 0; j < 4; j++) {
            cv.u = acc[i][j];
            o[2 * j]     = cv.f.x;
            o[2 * j + 1] = cv.f.y;
        }
        if (add_bias) {
            #pragma unroll
            for (int j = 0; j < 8; j++) o[j] += bias8[j];
        }
        float* dp = &dst[(size_t)grow * DD + tx * 8];
        *(float4*)&dp[0] = make_float4(o[0], o[1], o[2], o[3]);
        *(float4*)&dp[4] = make_float4(o[4], o[5], o[6], o[7]);
    }
}

// ---------------------------------------------------------------------------
// Edge kernel: one warp per edge, lane handles 4 consecutive features.
//   eta = sigmoid(K[tgt] + Q[src]); msg = eta * V[src]; red.v4 into out[tgt]
// ---------------------------------------------------------------------------
__global__ void __launch_bounds__(256) edge_kernel(
    const void* __restrict__ edge_index,
    const float* __restrict__ K, const float* __restrict__ Q,
    const float* __restrict__ V, float* __restrict__ out)
{
    int warp = (blockIdx.x * blockDim.x + threadIdx.x) >> 5;
    if (warp >= NE) return;
    int lane = threadIdx.x & 31;

    int src, tgt;
    if (g_is32) {
        const int* ei = (const int*)edge_index;
        src = ei[warp];
        tgt = ei[NE + warp];
    } else {
        const long long* ei = (const long long*)edge_index;
        src = (int)ei[warp];
        tgt = (int)ei[NE + warp];
    }

    int d0 = lane * 4;
    float4 kt = *(const float4*)&K[(size_t)tgt * DD + d0];
    float4 qs = *(const float4*)&Q[(size_t)src * DD + d0];
    float4 vs = *(const float4*)&V[(size_t)src * DD + d0];

    float4 m;
    m.x = vs.x / (1.f + __expf(-(kt.x + qs.x)));
    m.y = vs.y / (1.f + __expf(-(kt.y + qs.y)));
    m.z = vs.z / (1.f + __expf(-(kt.z + qs.z)));
    m.w = vs.w / (1.f + __expf(-(kt.w + qs.w)));

    float* o = &out[(size_t)tgt * DD + d0];
    asm volatile("red.global.add.v4.f32 [%0], {%1, %2, %3, %4};"
                 :: "l"(o), "f"(m.x), "f"(m.y), "f"(m.z), "f"(m.w)
                 : "memory");
}

// ---------------------------------------------------------------------------
extern "C" void kernel_launch(void* const* d_in, const int* in_sizes, int n_in,
                              void* d_out, int out_size)
{
    const float* x   = (const float*)d_in[0];
    const void*  ei  = d_in[1];
    const float* Wk1 = (const float*)d_in[2];
    const float* Wq1 = (const float*)d_in[3];
    const float* Wv1 = (const float*)d_in[4];
    const float* Ws1 = (const float*)d_in[5];
    const float* b1  = (const float*)d_in[6];
    const float* Wk2 = (const float*)d_in[7];
    const float* Wq2 = (const float*)d_in[8];
    const float* Wv2 = (const float*)d_in[9];
    const float* Ws2 = (const float*)d_in[10];
    const float* b2  = (const float*)d_in[11];
    float* out = (float*)d_out;

    float *pK, *pQ, *pV, *pH;
    cudaGetSymbolAddress((void**)&pK, g_K);
    cudaGetSymbolAddress((void**)&pQ, g_Q);
    cudaGetSymbolAddress((void**)&pV, g_V);
    cudaGetSymbolAddress((void**)&pH, g_H);

    detect_init_kernel<<<1, 1>>>();
    detect_kernel<<<(NE + 255) / 256, 256>>>((const unsigned int*)ei);

    dim3 ggrid((NN + BM - 1) / BM, 4);
    dim3 egrid((NE * 32 + 255) / 256);

    // ---- Layer 1 ----
    GemmArgs g1;
    g1.W[0] = Wk1; g1.W[1] = Wq1; g1.W[2] = Wv1; g1.W[3] = Ws1;
    g1.dst[0] = pK; g1.dst[1] = pQ; g1.dst[2] = pV; g1.dst[3] = pH;
    g1.bias = b1;
    gemm4_kernel<<<ggrid, 256>>>(x, g1, /*relu=*/0);
    edge_kernel<<<egrid, 256>>>(ei, pK, pQ, pV, pH);

    // ---- Layer 2 (ReLU fused into A-load) ----
    GemmArgs g2;
    g2.W[0] = Wk2; g2.W[1] = Wq2; g2.W[2] = Wv2; g2.W[3] = Ws2;
    g2.dst[0] = pK; g2.dst[1] = pQ; g2.dst[2] = pV; g2.dst[3] = out;
    g2.bias = b2;
    gemm4_kernel<<<ggrid, 256>>>(pH, g2, /*relu=*/1);
    edge_kernel<<<egrid, 256>>>(ei, pK, pQ, pV, out);
}

// round 3
// speedup vs baseline: 1.6028x; 1.0023x over previous
#include <cuda_runtime.h>
#include <cstddef>
#include <cstdint>

#define NN 50000
#define NE 400000
#define DD 128

// Scratch (device globals: allocation-free rule)
__device__ float g_K[NN * DD];
__device__ float g_Q[NN * DD];
__device__ float g_V[NN * DD];
__device__ float g_H[NN * DD];
__device__ int   g_is32;

struct GemmArgs {
    const float* W[4];
    float*       dst[4];   // dst[0..2] = K,Q,V ; dst[3] = skip accumulator
    const float* bias;     // added to dst[3]
};

// ---------------------------------------------------------------------------
// int32-vs-int64 edge_index detection (odd 32-bit words all zero => int64).
// ---------------------------------------------------------------------------
__global__ void detect_init_kernel() { g_is32 = 0; }

__global__ void detect_kernel(const unsigned int* __restrict__ w) {
    int i = blockIdx.x * blockDim.x + threadIdx.x;
    if (i >= NE) return;
    if (w[2 * i + 1] != 0u) atomicOr(&g_is32, 1);
}

// ---------------------------------------------------------------------------
// Fused 4-way projection GEMM using packed fma.rn.f32x2 (FFMA2).
//   dst[w] = act(A) @ W[w],  w = 0..3 ; dst[3] += bias (skip path)
// BM=128, BN=128(=D), BK=16. 256 threads, 8x8 micro-tile per thread.
// A stored in smem PRE-DUPLICATED as float2{a,a} so the FFMA2 broadcast
// operand needs no per-iteration packing. B read as natural f32x2 pairs.
// grid = (ceil(N/128), 4)
// ---------------------------------------------------------------------------
#define BM 128
#define BK 16

typedef unsigned long long u64;

__device__ __forceinline__ u64 ffma2(u64 a, u64 b, u64 c) {
    u64 d;
    asm("fma.rn.f32x2 %0, %1, %2, %3;" : "=l"(d) : "l"(a), "l"(b), "l"(c));
    return d;
}

__global__ void __launch_bounds__(256, 2) gemm4_kernel(
    const float* __restrict__ A, GemmArgs ga, int apply_relu)
{
    __shared__ float2 AsD[BM][BK + 1];   // [row][k], value duplicated {a,a}
    __shared__ float  Bs[BK][DD + 4];    // [k][col]

    const int w = blockIdx.y;
    const float* __restrict__ W = ga.W[w];
    float* __restrict__ dst = ga.dst[w];

    const int row0 = blockIdx.x * BM;
    const int t  = threadIdx.x;
    const int tx = t & 15;        // column group: cols tx*8 .. tx*8+7
    const int ty = t >> 4;        // row group:    rows ty*8 .. ty*8+7

    u64 acc[8][4];                // 8 rows x 4 f32x2 col-pairs
    #pragma unroll
    for (int i = 0; i < 8; i++)
        #pragma unroll
        for (int j = 0; j < 4; j++) acc[i][j] = 0ull;   // bitwise {0.f,0.f}

    for (int k0 = 0; k0 < DD; k0 += BK) {
        // ---- Load A tile (128 x 16): 512 float4, 2 per thread ----
        #pragma unroll
        for (int l = 0; l < 2; l++) {
            int idx = l * 256 + t;            // float4 index
            int r   = idx >> 2;               // row in tile (4 float4 per row)
            int c4  = (idx & 3) * 4;          // k offset
            int grow = row0 + r;
            float4 v = make_float4(0.f, 0.f, 0.f, 0.f);
            if (grow < NN) v = *(const float4*)&A[(size_t)grow * DD + k0 + c4];
            if (apply_relu) {
                v.x = fmaxf(v.x, 0.f); v.y = fmaxf(v.y, 0.f);
                v.z = fmaxf(v.z, 0.f); v.w = fmaxf(v.w, 0.f);
            }
            AsD[r][c4 + 0] = make_float2(v.x, v.x);
            AsD[r][c4 + 1] = make_float2(v.y, v.y);
            AsD[r][c4 + 2] = make_float2(v.z, v.z);
            AsD[r][c4 + 3] = make_float2(v.w, v.w);
        }
        // ---- Load B tile (16 x 128): 512 float4, 2 per thread ----
        #pragma unroll
        for (int l = 0; l < 2; l++) {
            int idx = l * 256 + t;
            int r   = idx >> 5;               // k row (32 float4 per row)
            int c4  = (idx & 31) * 4;
            float4 v = *(const float4*)&W[(size_t)(k0 + r) * DD + c4];
            *(float4*)&Bs[r][c4] = v;
        }
        __syncthreads();

        #pragma unroll
        for (int kk = 0; kk < BK; kk++) {
            u64 a[8], b[4];
            #pragma unroll
            for (int i = 0; i < 8; i++)
                a[i] = *(const u64*)&AsD[ty * 8 + i][kk];
            const float* brow = &Bs[kk][tx * 8];
            #pragma unroll
            for (int j = 0; j < 4; j++)
                b[j] = *(const u64*)&brow[2 * j];
            #pragma unroll
            for (int i = 0; i < 8; i++)
                #pragma unroll
                for (int j = 0; j < 4; j++)
                    acc[i][j] = ffma2(a[i], b[j], acc[i][j]);
        }
        __syncthreads();
    }

    // ---- Epilogue ----
    const bool add_bias = (w == 3);
    float bias8[8];
    if (add_bias) {
        #pragma unroll
        for (int j = 0; j < 8; j++) bias8[j] = ga.bias[tx * 8 + j];
    }

    union { u64 u; float2 f; } cv;
    #pragma unroll
    for (int i = 0; i < 8; i++) {
        int grow = row0 + ty * 8 + i;
        if (grow >= NN) break;
        float o[8];
        #pragma unroll
        for (int j = 0; j < 4; j++) {
            cv.u = acc[i][j];
            o[2 * j]     = cv.f.x;
            o[2 * j + 1] = cv.f.y;
        }
        if (add_bias) {
            #pragma unroll
            for (int j = 0; j < 8; j++) o[j] += bias8[j];
        }
        float* dp = &dst[(size_t)grow * DD + tx * 8];
        *(float4*)&dp[0] = make_float4(o[0], o[1], o[2], o[3]);
        *(float4*)&dp[4] = make_float4(o[4], o[5], o[6], o[7]);
    }
}

// ---------------------------------------------------------------------------
// Edge kernel: one warp per edge, lane handles 4 consecutive features.
//   eta = sigmoid(K[tgt] + Q[src]); msg = eta * V[src]; red.v4 into out[tgt]
// ---------------------------------------------------------------------------
__global__ void __launch_bounds__(256) edge_kernel(
    const void* __restrict__ edge_index,
    const float* __restrict__ K, const float* __restrict__ Q,
    const float* __restrict__ V, float* __restrict__ out)
{
    int warp = (blockIdx.x * blockDim.x + threadIdx.x) >> 5;
    if (warp >= NE) return;
    int lane = threadIdx.x & 31;

    int src, tgt;
    if (g_is32) {
        const int* ei = (const int*)edge_index;
        src = ei[warp];
        tgt = ei[NE + warp];
    } else {
        const long long* ei = (const long long*)edge_index;
        src = (int)ei[warp];
        tgt = (int)ei[NE + warp];
    }

    int d0 = lane * 4;
    float4 kt = *(const float4*)&K[(size_t)tgt * DD + d0];
    float4 qs = *(const float4*)&Q[(size_t)src * DD + d0];
    float4 vs = *(const float4*)&V[(size_t)src * DD + d0];

    float4 m;
    m.x = vs.x / (1.f + __expf(-(kt.x + qs.x)));
    m.y = vs.y / (1.f + __expf(-(kt.y + qs.y)));
    m.z = vs.z / (1.f + __expf(-(kt.z + qs.z)));
    m.w = vs.w / (1.f + __expf(-(kt.w + qs.w)));

    float* o = &out[(size_t)tgt * DD + d0];
    asm volatile("red.global.add.v4.f32 [%0], {%1, %2, %3, %4};"
                 :: "l"(o), "f"(m.x), "f"(m.y), "f"(m.z), "f"(m.w)
                 : "memory");
}

// ---------------------------------------------------------------------------
extern "C" void kernel_launch(void* const* d_in, const int* in_sizes, int n_in,
                              void* d_out, int out_size)
{
    const float* x   = (const float*)d_in[0];
    const void*  ei  = d_in[1];
    const float* Wk1 = (const float*)d_in[2];
    const float* Wq1 = (const float*)d_in[3];
    const float* Wv1 = (const float*)d_in[4];
    const float* Ws1 = (const float*)d_in[5];
    const float* b1  = (const float*)d_in[6];
    const float* Wk2 = (const float*)d_in[7];
    const float* Wq2 = (const float*)d_in[8];
    const float* Wv2 = (const float*)d_in[9];
    const float* Ws2 = (const float*)d_in[10];
    const float* b2  = (const float*)d_in[11];
    float* out = (float*)d_out;

    float *pK, *pQ, *pV, *pH;
    cudaGetSymbolAddress((void**)&pK, g_K);
    cudaGetSymbolAddress((void**)&pQ, g_Q);
    cudaGetSymbolAddress((void**)&pV, g_V);
    cudaGetSymbolAddress((void**)&pH, g_H);

    detect_init_kernel<<<1, 1>>>();
    detect_kernel<<<(NE + 255) / 256, 256>>>((const unsigned int*)ei);

    dim3 ggrid((NN + BM - 1) / BM, 4);
    dim3 egrid((NE * 32 + 255) / 256);

    // ---- Layer 1 ----
    GemmArgs g1;
    g1.W[0] = Wk1; g1.W[1] = Wq1; g1.W[2] = Wv1; g1.W[3] = Ws1;
    g1.dst[0] = pK; g1.dst[1] = pQ; g1.dst[2] = pV; g1.dst[3] = pH;
    g1.bias = b1;
    gemm4_kernel<<<ggrid, 256>>>(x, g1, /*relu=*/0);
    edge_kernel<<<egrid, 256>>>(ei, pK, pQ, pV, pH);

    // ---- Layer 2 (ReLU fused into A-load) ----
    GemmArgs g2;
    g2.W[0] = Wk2; g2.W[1] = Wq2; g2.W[2] = Wv2; g2.W[3] = Ws2;
    g2.dst[0] = pK; g2.dst[1] = pQ; g2.dst[2] = pV; g2.dst[3] = out;
    g2.bias = b2;
    gemm4_kernel<<<ggrid, 256>>>(pH, g2, /*relu=*/1);
    edge_kernel<<<egrid, 256>>>(ei, pK, pQ, pV, out);
}